// round 2
// baseline (speedup 1.0000x reference)
#include <cuda_runtime.h>

#define NN 100000
#define EE 1600000
#define FF 128
#define BN_EPS 1e-5f

// ---------------- device scratch (no allocs allowed) ----------------
__device__ int   g_is64;          // 1 if edge_index is int64, 0 if int32
__device__ int   g_cnt[NN];
__device__ int   g_off[NN + 1];
__device__ int   g_cur[NN];
__device__ int   g_bin[EE];
__device__ float g_t0[(size_t)NN * FF];   // x + agg0
__device__ float g_h [(size_t)NN * FF];   // relu(bn(gemm0))
__device__ float g_t1[(size_t)NN * FF];   // h + agg1

// ---------------- edge dtype probe ----------------
// int64 indices < 2^31  => all odd 32-bit words are 0.
// int32 indices         => odd words are random node ids, ~all nonzero.
__global__ void k_probe(const int* __restrict__ ei32) {
    __shared__ int any;
    if (threadIdx.x == 0) any = 0;
    __syncthreads();
    int w = ei32[threadIdx.x * 2 + 1];   // odd words of first 4096 ints
    if (w != 0) atomicOr(&any, 1);
    __syncthreads();
    if (threadIdx.x == 0) g_is64 = any ? 0 : 1;
}

__device__ __forceinline__ int edge_at(const void* ei, int idx) {
    if (g_is64) return (int)((const long long*)ei)[idx];
    return ((const int*)ei)[idx];
}

// ---------------- CSR build ----------------
__global__ void k_zero() {
    int i = blockIdx.x * blockDim.x + threadIdx.x;
    if (i < NN) g_cnt[i] = 0;
}

__global__ void k_count(const void* __restrict__ ei) {
    int e = blockIdx.x * blockDim.x + threadIdx.x;
    if (e < EE) {
        int dst = edge_at(ei, EE + e);
        atomicAdd(&g_cnt[dst], 1);
    }
}

// single-block exclusive scan of g_cnt -> g_off, g_cur
__global__ void k_scan() {
    __shared__ int sm[1024];
    const int CH = (NN + 1023) / 1024;   // 98
    int tid = threadIdx.x;
    int beg = tid * CH;
    int end = min(beg + CH, NN);
    int s = 0;
    for (int i = beg; i < end; i++) s += g_cnt[i];
    sm[tid] = s;
    __syncthreads();
    for (int off = 1; off < 1024; off <<= 1) {
        int v = (tid >= off) ? sm[tid - off] : 0;
        __syncthreads();
        sm[tid] += v;
        __syncthreads();
    }
    int run = (tid == 0) ? 0 : sm[tid - 1];
    for (int i = beg; i < end; i++) {
        g_off[i] = run;
        g_cur[i] = run;
        run += g_cnt[i];
    }
    if (tid == 1023) g_off[NN] = sm[1023];
}

__global__ void k_fill(const void* __restrict__ ei) {
    int e = blockIdx.x * blockDim.x + threadIdx.x;
    if (e < EE) {
        int src = edge_at(ei, e);
        int dst = edge_at(ei, EE + e);
        int p = atomicAdd(&g_cur[dst], 1);
        g_bin[p] = src;
    }
}

// ---------------- gather-reduce: T[i] = X[i] + sum_{s in bin(i)} X[s] ----------------
__global__ void k_gather(const float* __restrict__ X, float* __restrict__ T) {
    int w    = (blockIdx.x * blockDim.x + threadIdx.x) >> 5;  // node (warp per node)
    int lane = threadIdx.x & 31;
    if (w >= NN) return;
    const float4* __restrict__ Xr = (const float4*)X;
    float4 acc = Xr[(size_t)w * 32 + lane];
    int j   = g_off[w];
    int end = g_off[w + 1];
    for (; j + 4 <= end; j += 4) {
        int s0 = g_bin[j], s1 = g_bin[j + 1], s2 = g_bin[j + 2], s3 = g_bin[j + 3];
        float4 v0 = Xr[(size_t)s0 * 32 + lane];
        float4 v1 = Xr[(size_t)s1 * 32 + lane];
        float4 v2 = Xr[(size_t)s2 * 32 + lane];
        float4 v3 = Xr[(size_t)s3 * 32 + lane];
        acc.x += v0.x; acc.y += v0.y; acc.z += v0.z; acc.w += v0.w;
        acc.x += v1.x; acc.y += v1.y; acc.z += v1.z; acc.w += v1.w;
        acc.x += v2.x; acc.y += v2.y; acc.z += v2.z; acc.w += v2.w;
        acc.x += v3.x; acc.y += v3.y; acc.z += v3.z; acc.w += v3.w;
    }
    for (; j < end; j++) {
        int s = g_bin[j];
        float4 v = Xr[(size_t)s * 32 + lane];
        acc.x += v.x; acc.y += v.y; acc.z += v.z; acc.w += v.w;
    }
    ((float4*)T)[(size_t)w * 32 + lane] = acc;
}

// ---------------- GEMM: Out[M,128] = A[M,128] @ W[128,128] (+bias, optional BN+ReLU) ---
template <bool BNRELU>
__global__ void __launch_bounds__(256)
k_gemm(const float* __restrict__ A, const float* __restrict__ W,
       const float* __restrict__ bias,
       const float* __restrict__ gamma, const float* __restrict__ beta,
       const float* __restrict__ rmean, const float* __restrict__ rvar,
       float* __restrict__ Out) {
    __shared__ float Ws[8][128];
    __shared__ float As[8][132];

    int tid = threadIdx.x;
    int tx = tid & 15;
    int ty = tid >> 4;
    int row0 = blockIdx.x * 128;

    float acc[8][8];
#pragma unroll
    for (int i = 0; i < 8; i++)
#pragma unroll
        for (int j = 0; j < 8; j++) acc[i][j] = 0.f;

    int arow  = tid >> 1;
    int ahalf = tid & 1;
    int wrow  = tid >> 5;
    int wcol  = (tid & 31) * 4;

    for (int kb = 0; kb < 128; kb += 8) {
        __syncthreads();
        float4 av = make_float4(0.f, 0.f, 0.f, 0.f);
        int gr = row0 + arow;
        if (gr < NN) av = *(const float4*)&A[(size_t)gr * 128 + kb + ahalf * 4];
        As[ahalf * 4 + 0][arow] = av.x;
        As[ahalf * 4 + 1][arow] = av.y;
        As[ahalf * 4 + 2][arow] = av.z;
        As[ahalf * 4 + 3][arow] = av.w;
        *(float4*)&Ws[wrow][wcol] = *(const float4*)&W[(size_t)(kb + wrow) * 128 + wcol];
        __syncthreads();
#pragma unroll
        for (int kk = 0; kk < 8; kk++) {
            float a[8], w[8];
            *(float4*)(a)     = *(const float4*)&As[kk][ty * 8];
            *(float4*)(a + 4) = *(const float4*)&As[kk][ty * 8 + 4];
            *(float4*)(w)     = *(const float4*)&Ws[kk][tx * 8];
            *(float4*)(w + 4) = *(const float4*)&Ws[kk][tx * 8 + 4];
#pragma unroll
            for (int i = 0; i < 8; i++)
#pragma unroll
                for (int j = 0; j < 8; j++) acc[i][j] += a[i] * w[j];
        }
    }

    int col0 = tx * 8;
    float sc[8], sh[8];
#pragma unroll
    for (int j = 0; j < 8; j++) {
        if (BNRELU) {
            float g  = gamma[col0 + j];
            float iv = rsqrtf(rvar[col0 + j] + BN_EPS);
            sc[j] = g * iv;
            sh[j] = (bias[col0 + j] - rmean[col0 + j]) * sc[j] + beta[col0 + j];
        } else {
            sc[j] = 1.f;
            sh[j] = bias[col0 + j];
        }
    }
#pragma unroll
    for (int i = 0; i < 8; i++) {
        int gr = row0 + ty * 8 + i;
        if (gr < NN) {
            float o[8];
#pragma unroll
            for (int j = 0; j < 8; j++) {
                float v = acc[i][j] * sc[j] + sh[j];
                if (BNRELU) v = fmaxf(v, 0.f);
                o[j] = v;
            }
            *(float4*)&Out[(size_t)gr * 128 + col0]     = *(float4*)(o);
            *(float4*)&Out[(size_t)gr * 128 + col0 + 4] = *(float4*)(o + 4);
        }
    }
}

// ---------------- launch ----------------
extern "C" void kernel_launch(void* const* d_in, const int* in_sizes, int n_in,
                              void* d_out, int out_size) {
    const float* x     = (const float*)d_in[0];
    const void*  ei    = d_in[1];
    const float* w0    = (const float*)d_in[2];
    const float* b0    = (const float*)d_in[3];
    const float* gamma = (const float*)d_in[4];
    const float* beta  = (const float*)d_in[5];
    const float* rmean = (const float*)d_in[6];
    const float* rvar  = (const float*)d_in[7];
    const float* w1    = (const float*)d_in[8];
    const float* b1    = (const float*)d_in[9];
    float*       out   = (float*)d_out;

    float *t0, *h, *t1;
    cudaGetSymbolAddress((void**)&t0, g_t0);
    cudaGetSymbolAddress((void**)&h,  g_h);
    cudaGetSymbolAddress((void**)&t1, g_t1);

    // dtype probe + CSR build (by destination)
    k_probe<<<1, 2048 / 2>>>((const int*)ei);   // 1024 threads -> 2048 ints scanned
    k_zero <<<(NN + 255) / 256, 256>>>();
    k_count<<<(EE + 255) / 256, 256>>>(ei);
    k_scan <<<1, 1024>>>();
    k_fill <<<(EE + 255) / 256, 256>>>(ei);

    const int GATHER_BLKS = (NN + 7) / 8;
    const int GEMM_BLKS   = (NN + 127) / 128;

    k_gather<<<GATHER_BLKS, 256>>>(x, t0);
    k_gemm<true><<<GEMM_BLKS, 256>>>(t0, w0, b0, gamma, beta, rmean, rvar, h);

    k_gather<<<GATHER_BLKS, 256>>>(h, t1);
    k_gemm<false><<<GEMM_BLKS, 256>>>(t1, w1, b1, nullptr, nullptr, nullptr, nullptr, out);
}

// round 3
// speedup vs baseline: 1.4389x; 1.4389x over previous
#include <cuda_runtime.h>

#define NN 100000
#define EE 1600000
#define FF 128
#define BN_EPS 1e-5f

#define SCAN_B 256
#define NBLK ((NN + SCAN_B - 1) / SCAN_B)   // 391

// ---------------- device scratch (no allocs allowed) ----------------
__device__ int   g_is64;
__device__ int   g_cnt[NN];
__device__ int   g_off[NN + 1];
__device__ int   g_cur[NN];
__device__ int   g_bin[EE];
__device__ int   g_bsum[NBLK];
__device__ int   g_boff[NBLK + 1];
__device__ float g_t0[(size_t)NN * FF];
__device__ float g_h [(size_t)NN * FF];
__device__ float g_t1[(size_t)NN * FF];

// ---------------- edge dtype probe ----------------
__global__ void k_probe(const int* __restrict__ ei32) {
    __shared__ int any;
    if (threadIdx.x == 0) any = 0;
    __syncthreads();
    int w = ei32[threadIdx.x * 2 + 1];
    if (w != 0) atomicOr(&any, 1);
    __syncthreads();
    if (threadIdx.x == 0) g_is64 = any ? 0 : 1;
}

__device__ __forceinline__ int edge_at(const void* ei, int idx) {
    if (g_is64) return (int)((const long long*)ei)[idx];
    return ((const int*)ei)[idx];
}

// ---------------- CSR build ----------------
__global__ void k_zero() {
    int i = blockIdx.x * blockDim.x + threadIdx.x;
    if (i < NN) g_cnt[i] = 0;
}

__global__ void k_count(const void* __restrict__ ei) {
    int e = blockIdx.x * blockDim.x + threadIdx.x;
    if (e < EE) atomicAdd(&g_cnt[edge_at(ei, EE + e)], 1);
}

// phase 1: per-block sums of g_cnt
__global__ void k_bsum() {
    __shared__ int sm[SCAN_B];
    int i = blockIdx.x * SCAN_B + threadIdx.x;
    int v = (i < NN) ? g_cnt[i] : 0;
    sm[threadIdx.x] = v;
    __syncthreads();
    for (int off = SCAN_B / 2; off > 0; off >>= 1) {
        if (threadIdx.x < off) sm[threadIdx.x] += sm[threadIdx.x + off];
        __syncthreads();
    }
    if (threadIdx.x == 0) g_bsum[blockIdx.x] = sm[0];
}

// phase 2: one-block exclusive scan of the 391 block sums
__global__ void k_bscan() {
    __shared__ int sm[512];
    int tid = threadIdx.x;
    int v = (tid < NBLK) ? g_bsum[tid] : 0;
    sm[tid] = v;
    __syncthreads();
    for (int off = 1; off < 512; off <<= 1) {
        int u = (tid >= off) ? sm[tid - off] : 0;
        __syncthreads();
        sm[tid] += u;
        __syncthreads();
    }
    if (tid < NBLK) g_boff[tid] = sm[tid] - v;        // exclusive
    if (tid == NBLK - 1) g_boff[NBLK] = sm[tid];      // total
}

// phase 3: local exclusive scan within each block + block offset -> g_off/g_cur
__global__ void k_boffsets() {
    __shared__ int sm[SCAN_B];
    int tid = threadIdx.x;
    int i = blockIdx.x * SCAN_B + tid;
    int v = (i < NN) ? g_cnt[i] : 0;
    sm[tid] = v;
    __syncthreads();
    for (int off = 1; off < SCAN_B; off <<= 1) {
        int u = (tid >= off) ? sm[tid - off] : 0;
        __syncthreads();
        sm[tid] += u;
        __syncthreads();
    }
    int off0 = g_boff[blockIdx.x];
    if (i < NN) {
        int e = off0 + sm[tid] - v;
        g_off[i] = e;
        g_cur[i] = e;
    }
    if (i == NN - 1) g_off[NN] = g_boff[NBLK];
}

__global__ void k_fill(const void* __restrict__ ei) {
    int e = blockIdx.x * blockDim.x + threadIdx.x;
    if (e < EE) {
        int src = edge_at(ei, e);
        int dst = edge_at(ei, EE + e);
        int p = atomicAdd(&g_cur[dst], 1);
        g_bin[p] = src;
    }
}

// ---------------- gather-reduce: T[i] = X[i] + sum_{s in bin(i)} X[s] ----------------
__global__ void k_gather(const float* __restrict__ X, float* __restrict__ T) {
    int w    = (blockIdx.x * blockDim.x + threadIdx.x) >> 5;
    int lane = threadIdx.x & 31;
    if (w >= NN) return;
    const float4* __restrict__ Xr = (const float4*)X;
    float4 acc = Xr[(size_t)w * 32 + lane];
    int j   = g_off[w];
    int end = g_off[w + 1];
    for (; j + 4 <= end; j += 4) {
        int s0 = g_bin[j], s1 = g_bin[j + 1], s2 = g_bin[j + 2], s3 = g_bin[j + 3];
        float4 v0 = Xr[(size_t)s0 * 32 + lane];
        float4 v1 = Xr[(size_t)s1 * 32 + lane];
        float4 v2 = Xr[(size_t)s2 * 32 + lane];
        float4 v3 = Xr[(size_t)s3 * 32 + lane];
        acc.x += v0.x; acc.y += v0.y; acc.z += v0.z; acc.w += v0.w;
        acc.x += v1.x; acc.y += v1.y; acc.z += v1.z; acc.w += v1.w;
        acc.x += v2.x; acc.y += v2.y; acc.z += v2.z; acc.w += v2.w;
        acc.x += v3.x; acc.y += v3.y; acc.z += v3.z; acc.w += v3.w;
    }
    for (; j < end; j++) {
        int s = g_bin[j];
        float4 v = Xr[(size_t)s * 32 + lane];
        acc.x += v.x; acc.y += v.y; acc.z += v.z; acc.w += v.w;
    }
    ((float4*)T)[(size_t)w * 32 + lane] = acc;
}

// ---------------- GEMM: Out[M,128] = A[M,128] @ W[128,128] (+bias, optional BN+ReLU) ---
template <bool BNRELU>
__global__ void __launch_bounds__(256)
k_gemm(const float* __restrict__ A, const float* __restrict__ W,
       const float* __restrict__ bias,
       const float* __restrict__ gamma, const float* __restrict__ beta,
       const float* __restrict__ rmean, const float* __restrict__ rvar,
       float* __restrict__ Out) {
    __shared__ float Ws[8][128];
    __shared__ float As[8][132];

    int tid = threadIdx.x;
    int tx = tid & 15;
    int ty = tid >> 4;
    int row0 = blockIdx.x * 128;

    float acc[8][8];
#pragma unroll
    for (int i = 0; i < 8; i++)
#pragma unroll
        for (int j = 0; j < 8; j++) acc[i][j] = 0.f;

    int arow  = tid >> 1;
    int ahalf = tid & 1;
    int wrow  = tid >> 5;
    int wcol  = (tid & 31) * 4;

    for (int kb = 0; kb < 128; kb += 8) {
        __syncthreads();
        float4 av = make_float4(0.f, 0.f, 0.f, 0.f);
        int gr = row0 + arow;
        if (gr < NN) av = *(const float4*)&A[(size_t)gr * 128 + kb + ahalf * 4];
        As[ahalf * 4 + 0][arow] = av.x;
        As[ahalf * 4 + 1][arow] = av.y;
        As[ahalf * 4 + 2][arow] = av.z;
        As[ahalf * 4 + 3][arow] = av.w;
        *(float4*)&Ws[wrow][wcol] = *(const float4*)&W[(size_t)(kb + wrow) * 128 + wcol];
        __syncthreads();
#pragma unroll
        for (int kk = 0; kk < 8; kk++) {
            float a[8], w[8];
            *(float4*)(a)     = *(const float4*)&As[kk][ty * 8];
            *(float4*)(a + 4) = *(const float4*)&As[kk][ty * 8 + 4];
            *(float4*)(w)     = *(const float4*)&Ws[kk][tx * 8];
            *(float4*)(w + 4) = *(const float4*)&Ws[kk][tx * 8 + 4];
#pragma unroll
            for (int i = 0; i < 8; i++)
#pragma unroll
                for (int j = 0; j < 8; j++) acc[i][j] += a[i] * w[j];
        }
    }

    int col0 = tx * 8;
    float sc[8], sh[8];
#pragma unroll
    for (int j = 0; j < 8; j++) {
        if (BNRELU) {
            float g  = gamma[col0 + j];
            float iv = rsqrtf(rvar[col0 + j] + BN_EPS);
            sc[j] = g * iv;
            sh[j] = (bias[col0 + j] - rmean[col0 + j]) * sc[j] + beta[col0 + j];
        } else {
            sc[j] = 1.f;
            sh[j] = bias[col0 + j];
        }
    }
#pragma unroll
    for (int i = 0; i < 8; i++) {
        int gr = row0 + ty * 8 + i;
        if (gr < NN) {
            float o[8];
#pragma unroll
            for (int j = 0; j < 8; j++) {
                float v = acc[i][j] * sc[j] + sh[j];
                if (BNRELU) v = fmaxf(v, 0.f);
                o[j] = v;
            }
            *(float4*)&Out[(size_t)gr * 128 + col0]     = *(float4*)(o);
            *(float4*)&Out[(size_t)gr * 128 + col0 + 4] = *(float4*)(o + 4);
        }
    }
}

// ---------------- launch ----------------
extern "C" void kernel_launch(void* const* d_in, const int* in_sizes, int n_in,
                              void* d_out, int out_size) {
    const float* x     = (const float*)d_in[0];
    const void*  ei    = d_in[1];
    const float* w0    = (const float*)d_in[2];
    const float* b0    = (const float*)d_in[3];
    const float* gamma = (const float*)d_in[4];
    const float* beta  = (const float*)d_in[5];
    const float* rmean = (const float*)d_in[6];
    const float* rvar  = (const float*)d_in[7];
    const float* w1    = (const float*)d_in[8];
    const float* b1    = (const float*)d_in[9];
    float*       out   = (float*)d_out;

    float *t0, *h, *t1;
    cudaGetSymbolAddress((void**)&t0, g_t0);
    cudaGetSymbolAddress((void**)&h,  g_h);
    cudaGetSymbolAddress((void**)&t1, g_t1);

    // dtype probe + CSR build (by destination)
    k_probe<<<1, 1024>>>((const int*)ei);
    k_zero <<<(NN + 255) / 256, 256>>>();
    k_count<<<(EE + 255) / 256, 256>>>(ei);
    k_bsum    <<<NBLK, SCAN_B>>>();
    k_bscan   <<<1, 512>>>();
    k_boffsets<<<NBLK, SCAN_B>>>();
    k_fill <<<(EE + 255) / 256, 256>>>(ei);

    const int GATHER_BLKS = (NN + 7) / 8;
    const int GEMM_BLKS   = (NN + 127) / 128;

    k_gather<<<GATHER_BLKS, 256>>>(x, t0);
    k_gemm<true><<<GEMM_BLKS, 256>>>(t0, w0, b0, gamma, beta, rmean, rvar, h);

    k_gather<<<GATHER_BLKS, 256>>>(h, t1);
    k_gemm<false><<<GEMM_BLKS, 256>>>(t1, w1, b1, nullptr, nullptr, nullptr, nullptr, out);
}

// round 4
// speedup vs baseline: 1.4759x; 1.0257x over previous
#include <cuda_runtime.h>

#define NN 100000
#define EE 1600000
#define FF 128
#define BN_EPS 1e-5f

#define SCAN_B 256
#define NBLK ((NN + SCAN_B - 1) / SCAN_B)   // 391

typedef unsigned long long ull;

// ---------------- device scratch (no allocs allowed) ----------------
__device__ int   g_is64;
__device__ int   g_cnt[NN];
__device__ int   g_off[NN + 1];
__device__ int   g_cur[NN];
__device__ int   g_bin[EE];
__device__ int   g_bsum[NBLK];
__device__ int   g_boff[NBLK + 1];
__device__ float g_t0[(size_t)NN * FF];
__device__ float g_h [(size_t)NN * FF];
__device__ float g_t1[(size_t)NN * FF];

// ---------------- packed f32x2 helpers ----------------
__device__ __forceinline__ void fma2(ull& d, ull a, ull b) {
    asm("fma.rn.f32x2 %0, %1, %2, %0;" : "+l"(d) : "l"(a), "l"(b));
}
__device__ __forceinline__ ull pack2(float lo, float hi) {
    ull r;
    asm("mov.b64 %0, {%1, %2};" : "=l"(r) : "f"(lo), "f"(hi));
    return r;
}
__device__ __forceinline__ void unpack2(ull v, float& lo, float& hi) {
    asm("mov.b64 {%0, %1}, %2;" : "=f"(lo), "=f"(hi) : "l"(v));
}

// ---------------- edge dtype probe ----------------
__global__ void k_probe(const int* __restrict__ ei32) {
    __shared__ int any;
    if (threadIdx.x == 0) any = 0;
    __syncthreads();
    int w = ei32[threadIdx.x * 2 + 1];
    if (w != 0) atomicOr(&any, 1);
    __syncthreads();
    if (threadIdx.x == 0) g_is64 = any ? 0 : 1;
}

__device__ __forceinline__ int edge_at(const void* ei, int idx) {
    if (g_is64) return (int)((const long long*)ei)[idx];
    return ((const int*)ei)[idx];
}

// ---------------- CSR build ----------------
__global__ void k_zero() {
    int i = blockIdx.x * blockDim.x + threadIdx.x;
    if (i < NN) g_cnt[i] = 0;
}

__global__ void k_count(const void* __restrict__ ei) {
    int e = blockIdx.x * blockDim.x + threadIdx.x;
    if (e < EE) atomicAdd(&g_cnt[edge_at(ei, EE + e)], 1);
}

__global__ void k_bsum() {
    __shared__ int sm[SCAN_B];
    int i = blockIdx.x * SCAN_B + threadIdx.x;
    int v = (i < NN) ? g_cnt[i] : 0;
    sm[threadIdx.x] = v;
    __syncthreads();
    for (int off = SCAN_B / 2; off > 0; off >>= 1) {
        if (threadIdx.x < off) sm[threadIdx.x] += sm[threadIdx.x + off];
        __syncthreads();
    }
    if (threadIdx.x == 0) g_bsum[blockIdx.x] = sm[0];
}

__global__ void k_bscan() {
    __shared__ int sm[512];
    int tid = threadIdx.x;
    int v = (tid < NBLK) ? g_bsum[tid] : 0;
    sm[tid] = v;
    __syncthreads();
    for (int off = 1; off < 512; off <<= 1) {
        int u = (tid >= off) ? sm[tid - off] : 0;
        __syncthreads();
        sm[tid] += u;
        __syncthreads();
    }
    if (tid < NBLK) g_boff[tid] = sm[tid] - v;
    if (tid == NBLK - 1) g_boff[NBLK] = sm[tid];
}

__global__ void k_boffsets() {
    __shared__ int sm[SCAN_B];
    int tid = threadIdx.x;
    int i = blockIdx.x * SCAN_B + tid;
    int v = (i < NN) ? g_cnt[i] : 0;
    sm[tid] = v;
    __syncthreads();
    for (int off = 1; off < SCAN_B; off <<= 1) {
        int u = (tid >= off) ? sm[tid - off] : 0;
        __syncthreads();
        sm[tid] += u;
        __syncthreads();
    }
    int off0 = g_boff[blockIdx.x];
    if (i < NN) {
        int e = off0 + sm[tid] - v;
        g_off[i] = e;
        g_cur[i] = e;
    }
    if (i == NN - 1) g_off[NN] = g_boff[NBLK];
}

__global__ void k_fill(const void* __restrict__ ei) {
    int e = blockIdx.x * blockDim.x + threadIdx.x;
    if (e < EE) {
        int src = edge_at(ei, e);
        int dst = edge_at(ei, EE + e);
        int p = atomicAdd(&g_cur[dst], 1);
        g_bin[p] = src;
    }
}

// ---------------- gather-reduce: T[i] = X[i] + sum_{s in bin(i)} X[s] ----------------
__global__ void k_gather(const float* __restrict__ X, float* __restrict__ T) {
    int w    = (blockIdx.x * blockDim.x + threadIdx.x) >> 5;
    int lane = threadIdx.x & 31;
    if (w >= NN) return;
    const float4* __restrict__ Xr = (const float4*)X;
    float4 acc = Xr[(size_t)w * 32 + lane];
    int j   = g_off[w];
    int end = g_off[w + 1];
    for (; j + 4 <= end; j += 4) {
        int s0 = g_bin[j], s1 = g_bin[j + 1], s2 = g_bin[j + 2], s3 = g_bin[j + 3];
        float4 v0 = Xr[(size_t)s0 * 32 + lane];
        float4 v1 = Xr[(size_t)s1 * 32 + lane];
        float4 v2 = Xr[(size_t)s2 * 32 + lane];
        float4 v3 = Xr[(size_t)s3 * 32 + lane];
        acc.x += v0.x; acc.y += v0.y; acc.z += v0.z; acc.w += v0.w;
        acc.x += v1.x; acc.y += v1.y; acc.z += v1.z; acc.w += v1.w;
        acc.x += v2.x; acc.y += v2.y; acc.z += v2.z; acc.w += v2.w;
        acc.x += v3.x; acc.y += v3.y; acc.z += v3.z; acc.w += v3.w;
    }
    for (; j < end; j++) {
        int s = g_bin[j];
        float4 v = Xr[(size_t)s * 32 + lane];
        acc.x += v.x; acc.y += v.y; acc.z += v.z; acc.w += v.w;
    }
    ((float4*)T)[(size_t)w * 32 + lane] = acc;
}

// ---------------- GEMM with packed fma.rn.f32x2 ----------------
// Out[M,128] = A[M,128] @ W[128,128] (+bias, optional BN+ReLU)
// 128x128 tile, 256 threads, 8 rows x 8 cols per thread (cols as 4 packed pairs).
template <bool BNRELU>
__global__ void __launch_bounds__(256)
k_gemm(const float* __restrict__ A, const float* __restrict__ W,
       const float* __restrict__ bias,
       const float* __restrict__ gamma, const float* __restrict__ beta,
       const float* __restrict__ rmean, const float* __restrict__ rvar,
       float* __restrict__ Out) {
    __shared__ float Ws[8][128];
    __shared__ float As[8][132];

    int tid = threadIdx.x;
    int tx = tid & 15;
    int ty = tid >> 4;
    int row0 = blockIdx.x * 128;

    ull acc2[8][4];
#pragma unroll
    for (int i = 0; i < 8; i++)
#pragma unroll
        for (int j = 0; j < 4; j++) acc2[i][j] = 0ull;

    int arow  = tid >> 1;
    int ahalf = tid & 1;
    int wrow  = tid >> 5;
    int wcol  = (tid & 31) * 4;

    for (int kb = 0; kb < 128; kb += 8) {
        __syncthreads();
        float4 av = make_float4(0.f, 0.f, 0.f, 0.f);
        int gr = row0 + arow;
        if (gr < NN) av = *(const float4*)&A[(size_t)gr * 128 + kb + ahalf * 4];
        As[ahalf * 4 + 0][arow] = av.x;
        As[ahalf * 4 + 1][arow] = av.y;
        As[ahalf * 4 + 2][arow] = av.z;
        As[ahalf * 4 + 3][arow] = av.w;
        *(float4*)&Ws[wrow][wcol] = *(const float4*)&W[(size_t)(kb + wrow) * 128 + wcol];
        __syncthreads();
#pragma unroll
        for (int kk = 0; kk < 8; kk++) {
            float a[8];
            *(float4*)(a)     = *(const float4*)&As[kk][ty * 8];
            *(float4*)(a + 4) = *(const float4*)&As[kk][ty * 8 + 4];
            ull w2[4];
            const ull* wsrc = (const ull*)&Ws[kk][tx * 8];   // 32B-aligned
            w2[0] = wsrc[0]; w2[1] = wsrc[1]; w2[2] = wsrc[2]; w2[3] = wsrc[3];
#pragma unroll
            for (int i = 0; i < 8; i++) {
                ull ap = pack2(a[i], a[i]);
                fma2(acc2[i][0], ap, w2[0]);
                fma2(acc2[i][1], ap, w2[1]);
                fma2(acc2[i][2], ap, w2[2]);
                fma2(acc2[i][3], ap, w2[3]);
            }
        }
    }

    int col0 = tx * 8;
    float sc[8], sh[8];
#pragma unroll
    for (int j = 0; j < 8; j++) {
        if (BNRELU) {
            float g  = gamma[col0 + j];
            float iv = rsqrtf(rvar[col0 + j] + BN_EPS);
            sc[j] = g * iv;
            sh[j] = (bias[col0 + j] - rmean[col0 + j]) * sc[j] + beta[col0 + j];
        } else {
            sc[j] = 1.f;
            sh[j] = bias[col0 + j];
        }
    }
#pragma unroll
    for (int i = 0; i < 8; i++) {
        int gr = row0 + ty * 8 + i;
        if (gr < NN) {
            float o[8];
#pragma unroll
            for (int j = 0; j < 4; j++) {
                float lo, hi;
                unpack2(acc2[i][j], lo, hi);
                float v0 = lo * sc[2 * j]     + sh[2 * j];
                float v1 = hi * sc[2 * j + 1] + sh[2 * j + 1];
                if (BNRELU) { v0 = fmaxf(v0, 0.f); v1 = fmaxf(v1, 0.f); }
                o[2 * j] = v0; o[2 * j + 1] = v1;
            }
            *(float4*)&Out[(size_t)gr * 128 + col0]     = *(float4*)(o);
            *(float4*)&Out[(size_t)gr * 128 + col0 + 4] = *(float4*)(o + 4);
        }
    }
}

// ---------------- launch ----------------
extern "C" void kernel_launch(void* const* d_in, const int* in_sizes, int n_in,
                              void* d_out, int out_size) {
    const float* x     = (const float*)d_in[0];
    const void*  ei    = d_in[1];
    const float* w0    = (const float*)d_in[2];
    const float* b0    = (const float*)d_in[3];
    const float* gamma = (const float*)d_in[4];
    const float* beta  = (const float*)d_in[5];
    const float* rmean = (const float*)d_in[6];
    const float* rvar  = (const float*)d_in[7];
    const float* w1    = (const float*)d_in[8];
    const float* b1    = (const float*)d_in[9];
    float*       out   = (float*)d_out;

    float *t0, *h, *t1;
    cudaGetSymbolAddress((void**)&t0, g_t0);
    cudaGetSymbolAddress((void**)&h,  g_h);
    cudaGetSymbolAddress((void**)&t1, g_t1);

    k_probe<<<1, 1024>>>((const int*)ei);
    k_zero <<<(NN + 255) / 256, 256>>>();
    k_count<<<(EE + 255) / 256, 256>>>(ei);
    k_bsum    <<<NBLK, SCAN_B>>>();
    k_bscan   <<<1, 512>>>();
    k_boffsets<<<NBLK, SCAN_B>>>();
    k_fill <<<(EE + 255) / 256, 256>>>(ei);

    const int GATHER_BLKS = (NN + 7) / 8;
    const int GEMM_BLKS   = (NN + 127) / 128;

    k_gather<<<GATHER_BLKS, 256>>>(x, t0);
    k_gemm<true><<<GEMM_BLKS, 256>>>(t0, w0, b0, gamma, beta, rmean, rvar, h);

    k_gather<<<GATHER_BLKS, 256>>>(h, t1);
    k_gemm<false><<<GEMM_BLKS, 256>>>(t1, w1, b1, nullptr, nullptr, nullptr, nullptr, out);
}

// round 6
// speedup vs baseline: 1.5118x; 1.0243x over previous
#include <cuda_runtime.h>

#define NN 100000
#define EE 1600000
#define FF 128
#define BN_EPS 1e-5f

#define SCAN_B 256
#define NBLK ((NN + SCAN_B - 1) / SCAN_B)   // 391

#define KCH 16
#define APAD 132
// dynamic smem: W[128*128] + As[2][KCH][APAD]
#define SMEM_W_FLOATS (128 * 128)
#define SMEM_A_FLOATS (2 * KCH * APAD)
#define SMEM_BYTES ((SMEM_W_FLOATS + SMEM_A_FLOATS) * 4)

typedef unsigned long long ull;

// ---------------- device scratch (no allocs allowed) ----------------
__device__ int   g_is64;
__device__ int   g_cnt[NN];
__device__ int   g_off[NN + 1];
__device__ int   g_cur[NN];
__device__ int   g_bin[EE];
__device__ int   g_bsum[NBLK];
__device__ int   g_boff[NBLK + 1];
__device__ float g_t0[(size_t)NN * FF];
__device__ float g_h [(size_t)NN * FF];
__device__ float g_t1[(size_t)NN * FF];

// ---------------- packed f32x2 helpers ----------------
__device__ __forceinline__ void fma2(ull& d, ull a, ull b) {
    asm("fma.rn.f32x2 %0, %1, %2, %0;" : "+l"(d) : "l"(a), "l"(b));
}
__device__ __forceinline__ ull pack2(float lo, float hi) {
    ull r;
    asm("mov.b64 %0, {%1, %2};" : "=l"(r) : "f"(lo), "f"(hi));
    return r;
}
__device__ __forceinline__ void unpack2(ull v, float& lo, float& hi) {
    asm("mov.b64 {%0, %1}, %2;" : "=f"(lo), "=f"(hi) : "l"(v));
}

// ---------------- edge dtype probe ----------------
__global__ void k_probe(const int* __restrict__ ei32) {
    __shared__ int any;
    if (threadIdx.x == 0) any = 0;
    __syncthreads();
    int w = ei32[threadIdx.x * 2 + 1];
    if (w != 0) atomicOr(&any, 1);
    __syncthreads();
    if (threadIdx.x == 0) g_is64 = any ? 0 : 1;
}

__device__ __forceinline__ int edge_at(const void* ei, int idx) {
    if (g_is64) return (int)((const long long*)ei)[idx];
    return ((const int*)ei)[idx];
}

// ---------------- CSR build ----------------
__global__ void k_count(const void* __restrict__ ei) {
    int e = blockIdx.x * blockDim.x + threadIdx.x;
    if (e < EE) atomicAdd(&g_cnt[edge_at(ei, EE + e)], 1);
}

__global__ void k_bsum() {
    __shared__ int sm[SCAN_B];
    int i = blockIdx.x * SCAN_B + threadIdx.x;
    int v = (i < NN) ? g_cnt[i] : 0;
    sm[threadIdx.x] = v;
    __syncthreads();
    for (int off = SCAN_B / 2; off > 0; off >>= 1) {
        if (threadIdx.x < off) sm[threadIdx.x] += sm[threadIdx.x + off];
        __syncthreads();
    }
    if (threadIdx.x == 0) g_bsum[blockIdx.x] = sm[0];
}

__global__ void k_bscan() {
    __shared__ int sm[512];
    int tid = threadIdx.x;
    int v = (tid < NBLK) ? g_bsum[tid] : 0;
    sm[tid] = v;
    __syncthreads();
    for (int off = 1; off < 512; off <<= 1) {
        int u = (tid >= off) ? sm[tid - off] : 0;
        __syncthreads();
        sm[tid] += u;
        __syncthreads();
    }
    if (tid < NBLK) g_boff[tid] = sm[tid] - v;
    if (tid == NBLK - 1) g_boff[NBLK] = sm[tid];
}

__global__ void k_boffsets() {
    __shared__ int sm[SCAN_B];
    int tid = threadIdx.x;
    int i = blockIdx.x * SCAN_B + tid;
    int v = (i < NN) ? g_cnt[i] : 0;
    sm[tid] = v;
    __syncthreads();
    for (int off = 1; off < SCAN_B; off <<= 1) {
        int u = (tid >= off) ? sm[tid - off] : 0;
        __syncthreads();
        sm[tid] += u;
        __syncthreads();
    }
    int off0 = g_boff[blockIdx.x];
    if (i < NN) {
        int e = off0 + sm[tid] - v;
        g_off[i] = e;
        g_cur[i] = e;
    }
    if (i == NN - 1) g_off[NN] = g_boff[NBLK];
}

__global__ void k_fill(const void* __restrict__ ei) {
    int e = blockIdx.x * blockDim.x + threadIdx.x;
    if (e < EE) {
        int src = edge_at(ei, e);
        int dst = edge_at(ei, EE + e);
        int p = atomicAdd(&g_cur[dst], 1);
        g_bin[p] = src;
    }
}

// ---------------- gather-reduce: T[i] = X[i] + sum_{s in bin(i)} X[s] ----------------
__global__ void k_gather(const float* __restrict__ X, float* __restrict__ T) {
    int w    = (blockIdx.x * blockDim.x + threadIdx.x) >> 5;
    int lane = threadIdx.x & 31;
    if (w >= NN) return;
    const float4* __restrict__ Xr = (const float4*)X;
    float4 acc = Xr[(size_t)w * 32 + lane];
    int j   = g_off[w];
    int end = g_off[w + 1];
    for (; j + 4 <= end; j += 4) {
        int s0 = g_bin[j], s1 = g_bin[j + 1], s2 = g_bin[j + 2], s3 = g_bin[j + 3];
        float4 v0 = Xr[(size_t)s0 * 32 + lane];
        float4 v1 = Xr[(size_t)s1 * 32 + lane];
        float4 v2 = Xr[(size_t)s2 * 32 + lane];
        float4 v3 = Xr[(size_t)s3 * 32 + lane];
        acc.x += v0.x; acc.y += v0.y; acc.z += v0.z; acc.w += v0.w;
        acc.x += v1.x; acc.y += v1.y; acc.z += v1.z; acc.w += v1.w;
        acc.x += v2.x; acc.y += v2.y; acc.z += v2.z; acc.w += v2.w;
        acc.x += v3.x; acc.y += v3.y; acc.z += v3.z; acc.w += v3.w;
    }
    for (; j < end; j++) {
        int s = g_bin[j];
        float4 v = Xr[(size_t)s * 32 + lane];
        acc.x += v.x; acc.y += v.y; acc.z += v.z; acc.w += v.w;
    }
    ((float4*)T)[(size_t)w * 32 + lane] = acc;
}

// ---------------- GEMM: full-W smem + double-buffered A, 1 sync/chunk --------------
// Out[M,128] = A[M,128] @ W[128,128] (+bias, optional BN+ReLU)
// 128x128 tile, 256 threads, 8x8 per thread, packed f32x2 accumulation.
template <bool BNRELU>
__global__ void __launch_bounds__(256)
k_gemm(const float* __restrict__ A, const float* __restrict__ W,
       const float* __restrict__ bias,
       const float* __restrict__ gamma, const float* __restrict__ beta,
       const float* __restrict__ rmean, const float* __restrict__ rvar,
       float* __restrict__ Out) {
    extern __shared__ float smem[];
    float* Ws = smem;                       // [128][128]
    float* As = smem + SMEM_W_FLOATS;       // [2][KCH][APAD]

    int tid = threadIdx.x;
    int tx = tid & 15;
    int ty = tid >> 4;
    int row0 = blockIdx.x * 128;

    // preload full W (64 KB), coalesced
#pragma unroll
    for (int i = 0; i < 16; i++)
        ((float4*)Ws)[tid + i * 256] = ((const float4*)W)[tid + i * 256];

    ull acc2[8][4];
#pragma unroll
    for (int i = 0; i < 8; i++)
#pragma unroll
        for (int j = 0; j < 4; j++) acc2[i][j] = 0ull;

    // A staging: 2 items per thread per chunk
    int it_row0 = tid >> 2;            // item0 row (0..63)
    int it_q0   = tid & 3;             // which float4 within 16-wide k chunk
    // item1 = tid + 256 -> row + 64, same q
    float4 pre0, pre1;

    // load chunk 0
    {
        int gr0 = row0 + it_row0;
        int gr1 = gr0 + 64;
        int col = it_q0 * 4;
        pre0 = (gr0 < NN) ? *(const float4*)&A[(size_t)gr0 * 128 + col]
                          : make_float4(0.f, 0.f, 0.f, 0.f);
        pre1 = (gr1 < NN) ? *(const float4*)&A[(size_t)gr1 * 128 + col]
                          : make_float4(0.f, 0.f, 0.f, 0.f);
    }

    for (int kb = 0; kb < 8; kb++) {
        float* Ab = As + (kb & 1) * (KCH * APAD);
        // store prefetched chunk (transposed: As[k][row])
        {
            int k0 = it_q0 * 4;
            float* p0 = Ab + (size_t)k0 * APAD + it_row0;
            p0[0 * APAD] = pre0.x; p0[1 * APAD] = pre0.y;
            p0[2 * APAD] = pre0.z; p0[3 * APAD] = pre0.w;
            float* p1 = p0 + 64;
            p1[0 * APAD] = pre1.x; p1[1 * APAD] = pre1.y;
            p1[2 * APAD] = pre1.z; p1[3 * APAD] = pre1.w;
        }
        __syncthreads();
        // prefetch next chunk into registers (overlaps with compute below)
        if (kb < 7) {
            int gr0 = row0 + it_row0;
            int gr1 = gr0 + 64;
            int col = (kb + 1) * KCH + it_q0 * 4;
            pre0 = (gr0 < NN) ? *(const float4*)&A[(size_t)gr0 * 128 + col]
                              : make_float4(0.f, 0.f, 0.f, 0.f);
            pre1 = (gr1 < NN) ? *(const float4*)&A[(size_t)gr1 * 128 + col]
                              : make_float4(0.f, 0.f, 0.f, 0.f);
        }
        // compute 16 k-steps from smem
#pragma unroll
        for (int kk = 0; kk < KCH; kk++) {
            float a[8];
            *(float4*)(a)     = *(const float4*)&Ab[(size_t)kk * APAD + ty * 8];
            *(float4*)(a + 4) = *(const float4*)&Ab[(size_t)kk * APAD + ty * 8 + 4];
            const ull* wsrc = (const ull*)&Ws[(size_t)(kb * KCH + kk) * 128 + tx * 8];
            ull w2[4];
            w2[0] = wsrc[0]; w2[1] = wsrc[1]; w2[2] = wsrc[2]; w2[3] = wsrc[3];
#pragma unroll
            for (int i = 0; i < 8; i++) {
                ull ap = pack2(a[i], a[i]);
                fma2(acc2[i][0], ap, w2[0]);
                fma2(acc2[i][1], ap, w2[1]);
                fma2(acc2[i][2], ap, w2[2]);
                fma2(acc2[i][3], ap, w2[3]);
            }
        }
    }

    int col0 = tx * 8;
    float sc[8], sh[8];
#pragma unroll
    for (int j = 0; j < 8; j++) {
        if (BNRELU) {
            float g  = gamma[col0 + j];
            float iv = rsqrtf(rvar[col0 + j] + BN_EPS);
            sc[j] = g * iv;
            sh[j] = (bias[col0 + j] - rmean[col0 + j]) * sc[j] + beta[col0 + j];
        } else {
            sc[j] = 1.f;
            sh[j] = bias[col0 + j];
        }
    }
#pragma unroll
    for (int i = 0; i < 8; i++) {
        int gr = row0 + ty * 8 + i;
        if (gr < NN) {
            float o[8];
#pragma unroll
            for (int j = 0; j < 4; j++) {
                float lo, hi;
                unpack2(acc2[i][j], lo, hi);
                float v0 = lo * sc[2 * j]     + sh[2 * j];
                float v1 = hi * sc[2 * j + 1] + sh[2 * j + 1];
                if (BNRELU) { v0 = fmaxf(v0, 0.f); v1 = fmaxf(v1, 0.f); }
                o[2 * j] = v0; o[2 * j + 1] = v1;
            }
            *(float4*)&Out[(size_t)gr * 128 + col0]     = *(float4*)(o);
            *(float4*)&Out[(size_t)gr * 128 + col0 + 4] = *(float4*)(o + 4);
        }
    }
}

// ---------------- launch ----------------
extern "C" void kernel_launch(void* const* d_in, const int* in_sizes, int n_in,
                              void* d_out, int out_size) {
    const float* x     = (const float*)d_in[0];
    const void*  ei    = d_in[1];
    const float* w0    = (const float*)d_in[2];
    const float* b0    = (const float*)d_in[3];
    const float* gamma = (const float*)d_in[4];
    const float* beta  = (const float*)d_in[5];
    const float* rmean = (const float*)d_in[6];
    const float* rvar  = (const float*)d_in[7];
    const float* w1    = (const float*)d_in[8];
    const float* b1    = (const float*)d_in[9];
    float*       out   = (float*)d_out;

    float *t0, *h, *t1;
    int* cntp;
    cudaGetSymbolAddress((void**)&t0, g_t0);
    cudaGetSymbolAddress((void**)&h,  g_h);
    cudaGetSymbolAddress((void**)&t1, g_t1);
    cudaGetSymbolAddress((void**)&cntp, g_cnt);

    cudaFuncSetAttribute(k_gemm<true>,  cudaFuncAttributeMaxDynamicSharedMemorySize, SMEM_BYTES);
    cudaFuncSetAttribute(k_gemm<false>, cudaFuncAttributeMaxDynamicSharedMemorySize, SMEM_BYTES);

    k_probe<<<1, 1024>>>((const int*)ei);
    cudaMemsetAsync(cntp, 0, NN * sizeof(int));
    k_count<<<(EE + 255) / 256, 256>>>(ei);
    k_bsum    <<<NBLK, SCAN_B>>>();
    k_bscan   <<<1, 512>>>();
    k_boffsets<<<NBLK, SCAN_B>>>();
    k_fill <<<(EE + 255) / 256, 256>>>(ei);

    const int GATHER_BLKS = (NN + 7) / 8;
    const int GEMM_BLKS   = (NN + 127) / 128;

    k_gather<<<GATHER_BLKS, 256>>>(x, t0);
    k_gemm<true><<<GEMM_BLKS, 256, SMEM_BYTES>>>(t0, w0, b0, gamma, beta, rmean, rvar, h);

    k_gather<<<GATHER_BLKS, 256>>>(h, t1);
    k_gemm<false><<<GEMM_BLKS, 256, SMEM_BYTES>>>(t1, w1, b1, nullptr, nullptr, nullptr, nullptr, out);
}

// round 7
// speedup vs baseline: 1.5850x; 1.0484x over previous
#include <cuda_runtime.h>
#include <cuda_fp16.h>

#define NN 100000
#define EE 1600000
#define FF 128
#define BN_EPS 1e-5f

#define SCAN_B 256
#define NBLK ((NN + SCAN_B - 1) / SCAN_B)   // 391

#define KCH 16
#define APAD 132
#define SMEM_W_FLOATS (128 * 128)
#define SMEM_A_FLOATS (2 * KCH * APAD)
#define SMEM_BYTES ((SMEM_W_FLOATS + SMEM_A_FLOATS) * 4)

typedef unsigned long long ull;

// ---------------- device scratch (no allocs allowed) ----------------
__device__ int    g_is64;
__device__ int    g_cnt[NN];
__device__ int    g_off[NN + 1];
__device__ int    g_cur[NN];
__device__ int    g_bin[EE];
__device__ int    g_bsum[NBLK];
__device__ int    g_boff[NBLK + 1];
__device__ __half g_xh[(size_t)NN * FF];   // fp16 copy of x
__device__ __half g_hh[(size_t)NN * FF];   // fp16 h (gemm0 out)
__device__ float  g_t0[(size_t)NN * FF];   // x + agg0 (fp32)
__device__ float  g_t1[(size_t)NN * FF];   // h + agg1 (fp32)

// ---------------- packed f32x2 helpers ----------------
__device__ __forceinline__ void fma2(ull& d, ull a, ull b) {
    asm("fma.rn.f32x2 %0, %1, %2, %0;" : "+l"(d) : "l"(a), "l"(b));
}
__device__ __forceinline__ ull pack2(float lo, float hi) {
    ull r;
    asm("mov.b64 %0, {%1, %2};" : "=l"(r) : "f"(lo), "f"(hi));
    return r;
}
__device__ __forceinline__ void unpack2(ull v, float& lo, float& hi) {
    asm("mov.b64 {%0, %1}, %2;" : "=f"(lo), "=f"(hi) : "l"(v));
}

// ---------------- edge dtype probe ----------------
__global__ void k_probe(const int* __restrict__ ei32) {
    __shared__ int any;
    if (threadIdx.x == 0) any = 0;
    __syncthreads();
    int w = ei32[threadIdx.x * 2 + 1];
    if (w != 0) atomicOr(&any, 1);
    __syncthreads();
    if (threadIdx.x == 0) g_is64 = any ? 0 : 1;
}

__device__ __forceinline__ int edge_at(const void* ei, int idx) {
    if (g_is64) return (int)((const long long*)ei)[idx];
    return ((const int*)ei)[idx];
}

// ---------------- CSR build ----------------
__global__ void k_count(const void* __restrict__ ei) {
    int e = blockIdx.x * blockDim.x + threadIdx.x;
    if (e < EE) atomicAdd(&g_cnt[edge_at(ei, EE + e)], 1);
}

__global__ void k_bsum() {
    __shared__ int sm[SCAN_B];
    int i = blockIdx.x * SCAN_B + threadIdx.x;
    int v = (i < NN) ? g_cnt[i] : 0;
    sm[threadIdx.x] = v;
    __syncthreads();
    for (int off = SCAN_B / 2; off > 0; off >>= 1) {
        if (threadIdx.x < off) sm[threadIdx.x] += sm[threadIdx.x + off];
        __syncthreads();
    }
    if (threadIdx.x == 0) g_bsum[blockIdx.x] = sm[0];
}

__global__ void k_bscan() {
    __shared__ int sm[512];
    int tid = threadIdx.x;
    int v = (tid < NBLK) ? g_bsum[tid] : 0;
    sm[tid] = v;
    __syncthreads();
    for (int off = 1; off < 512; off <<= 1) {
        int u = (tid >= off) ? sm[tid - off] : 0;
        __syncthreads();
        sm[tid] += u;
        __syncthreads();
    }
    if (tid < NBLK) g_boff[tid] = sm[tid] - v;
    if (tid == NBLK - 1) g_boff[NBLK] = sm[tid];
}

__global__ void k_boffsets() {
    __shared__ int sm[SCAN_B];
    int tid = threadIdx.x;
    int i = blockIdx.x * SCAN_B + tid;
    int v = (i < NN) ? g_cnt[i] : 0;
    sm[tid] = v;
    __syncthreads();
    for (int off = 1; off < SCAN_B; off <<= 1) {
        int u = (tid >= off) ? sm[tid - off] : 0;
        __syncthreads();
        sm[tid] += u;
        __syncthreads();
    }
    int off0 = g_boff[blockIdx.x];
    if (i < NN) {
        int e = off0 + sm[tid] - v;
        g_off[i] = e;
        g_cur[i] = e;
    }
    if (i == NN - 1) g_off[NN] = g_boff[NBLK];
}

__global__ void k_fill(const void* __restrict__ ei) {
    int e = blockIdx.x * blockDim.x + threadIdx.x;
    if (e < EE) {
        int src = edge_at(ei, e);
        int dst = edge_at(ei, EE + e);
        int p = atomicAdd(&g_cur[dst], 1);
        g_bin[p] = src;
    }
}

// ---------------- fp32 -> fp16 table conversion ----------------
__global__ void k_tohalf(const float* __restrict__ X, __half* __restrict__ Y) {
    int i = blockIdx.x * blockDim.x + threadIdx.x;     // over N*F/4
    if (i < NN * FF / 4) {
        float4 v = ((const float4*)X)[i];
        __half2 a = __floats2half2_rn(v.x, v.y);
        __half2 b = __floats2half2_rn(v.z, v.w);
        uint2 o;
        o.x = *(unsigned*)&a;
        o.y = *(unsigned*)&b;
        ((uint2*)Y)[i] = o;
    }
}

// ---------------- gather-reduce (fp16 in, fp32 out) ----------------
// T[i] = Xh[i] + sum_{s in bin(i)} Xh[s];  row = 128 halves = 32 uint2 lanes
__global__ void k_gather_h(const __half* __restrict__ Xh, float* __restrict__ T) {
    int w    = (blockIdx.x * blockDim.x + threadIdx.x) >> 5;
    int lane = threadIdx.x & 31;
    if (w >= NN) return;
    const uint2* __restrict__ Xr = (const uint2*)Xh;   // 4 halves per lane

    float4 acc;
    {
        uint2 s = Xr[(size_t)w * 32 + lane];
        float2 lo = __half22float2(*(__half2*)&s.x);
        float2 hi = __half22float2(*(__half2*)&s.y);
        acc = make_float4(lo.x, lo.y, hi.x, hi.y);
    }

    int j   = g_off[w];
    int end = g_off[w + 1];
    for (; j + 8 <= end; j += 8) {
        uint2 v[8];
#pragma unroll
        for (int q = 0; q < 8; q++) {
            int s = g_bin[j + q];
            v[q] = Xr[(size_t)s * 32 + lane];
        }
#pragma unroll
        for (int q = 0; q < 8; q++) {
            float2 lo = __half22float2(*(__half2*)&v[q].x);
            float2 hi = __half22float2(*(__half2*)&v[q].y);
            acc.x += lo.x; acc.y += lo.y; acc.z += hi.x; acc.w += hi.y;
        }
    }
    for (; j < end; j++) {
        int s = g_bin[j];
        uint2 vv = Xr[(size_t)s * 32 + lane];
        float2 lo = __half22float2(*(__half2*)&vv.x);
        float2 hi = __half22float2(*(__half2*)&vv.y);
        acc.x += lo.x; acc.y += lo.y; acc.z += hi.x; acc.w += hi.y;
    }
    ((float4*)T)[(size_t)w * 32 + lane] = acc;
}

// ---------------- GEMM: full-W smem + double-buffered A ----------------
// Out = A[M,128] @ W[128,128] (+bias). BNRELU variant applies BN+ReLU and
// writes fp16 (consumed only by the next gather); plain variant writes fp32.
template <bool BNRELU>
__global__ void __launch_bounds__(256)
k_gemm(const float* __restrict__ A, const float* __restrict__ W,
       const float* __restrict__ bias,
       const float* __restrict__ gamma, const float* __restrict__ beta,
       const float* __restrict__ rmean, const float* __restrict__ rvar,
       float* __restrict__ OutF, __half* __restrict__ OutH) {
    extern __shared__ float smem[];
    float* Ws = smem;                       // [128][128]
    float* As = smem + SMEM_W_FLOATS;       // [2][KCH][APAD]

    int tid = threadIdx.x;
    int tx = tid & 15;
    int ty = tid >> 4;
    int row0 = blockIdx.x * 128;

#pragma unroll
    for (int i = 0; i < 16; i++)
        ((float4*)Ws)[tid + i * 256] = ((const float4*)W)[tid + i * 256];

    ull acc2[8][4];
#pragma unroll
    for (int i = 0; i < 8; i++)
#pragma unroll
        for (int j = 0; j < 4; j++) acc2[i][j] = 0ull;

    int it_row0 = tid >> 2;
    int it_q0   = tid & 3;
    float4 pre0, pre1;
    {
        int gr0 = row0 + it_row0;
        int gr1 = gr0 + 64;
        int col = it_q0 * 4;
        pre0 = (gr0 < NN) ? *(const float4*)&A[(size_t)gr0 * 128 + col]
                          : make_float4(0.f, 0.f, 0.f, 0.f);
        pre1 = (gr1 < NN) ? *(const float4*)&A[(size_t)gr1 * 128 + col]
                          : make_float4(0.f, 0.f, 0.f, 0.f);
    }

    for (int kb = 0; kb < 8; kb++) {
        float* Ab = As + (kb & 1) * (KCH * APAD);
        {
            int k0 = it_q0 * 4;
            float* p0 = Ab + (size_t)k0 * APAD + it_row0;
            p0[0 * APAD] = pre0.x; p0[1 * APAD] = pre0.y;
            p0[2 * APAD] = pre0.z; p0[3 * APAD] = pre0.w;
            float* p1 = p0 + 64;
            p1[0 * APAD] = pre1.x; p1[1 * APAD] = pre1.y;
            p1[2 * APAD] = pre1.z; p1[3 * APAD] = pre1.w;
        }
        __syncthreads();
        if (kb < 7) {
            int gr0 = row0 + it_row0;
            int gr1 = gr0 + 64;
            int col = (kb + 1) * KCH + it_q0 * 4;
            pre0 = (gr0 < NN) ? *(const float4*)&A[(size_t)gr0 * 128 + col]
                              : make_float4(0.f, 0.f, 0.f, 0.f);
            pre1 = (gr1 < NN) ? *(const float4*)&A[(size_t)gr1 * 128 + col]
                              : make_float4(0.f, 0.f, 0.f, 0.f);
        }
#pragma unroll
        for (int kk = 0; kk < KCH; kk++) {
            float a[8];
            *(float4*)(a)     = *(const float4*)&Ab[(size_t)kk * APAD + ty * 8];
            *(float4*)(a + 4) = *(const float4*)&Ab[(size_t)kk * APAD + ty * 8 + 4];
            const ull* wsrc = (const ull*)&Ws[(size_t)(kb * KCH + kk) * 128 + tx * 8];
            ull w2[4];
            w2[0] = wsrc[0]; w2[1] = wsrc[1]; w2[2] = wsrc[2]; w2[3] = wsrc[3];
#pragma unroll
            for (int i = 0; i < 8; i++) {
                ull ap = pack2(a[i], a[i]);
                fma2(acc2[i][0], ap, w2[0]);
                fma2(acc2[i][1], ap, w2[1]);
                fma2(acc2[i][2], ap, w2[2]);
                fma2(acc2[i][3], ap, w2[3]);
            }
        }
    }

    int col0 = tx * 8;
    float sc[8], sh[8];
#pragma unroll
    for (int j = 0; j < 8; j++) {
        if (BNRELU) {
            float g  = gamma[col0 + j];
            float iv = rsqrtf(rvar[col0 + j] + BN_EPS);
            sc[j] = g * iv;
            sh[j] = (bias[col0 + j] - rmean[col0 + j]) * sc[j] + beta[col0 + j];
        } else {
            sc[j] = 1.f;
            sh[j] = bias[col0 + j];
        }
    }
#pragma unroll
    for (int i = 0; i < 8; i++) {
        int gr = row0 + ty * 8 + i;
        if (gr < NN) {
            float o[8];
#pragma unroll
            for (int j = 0; j < 4; j++) {
                float lo, hi;
                unpack2(acc2[i][j], lo, hi);
                float v0 = lo * sc[2 * j]     + sh[2 * j];
                float v1 = hi * sc[2 * j + 1] + sh[2 * j + 1];
                if (BNRELU) { v0 = fmaxf(v0, 0.f); v1 = fmaxf(v1, 0.f); }
                o[2 * j] = v0; o[2 * j + 1] = v1;
            }
            if (BNRELU) {
                __half2 h0 = __floats2half2_rn(o[0], o[1]);
                __half2 h1 = __floats2half2_rn(o[2], o[3]);
                __half2 h2 = __floats2half2_rn(o[4], o[5]);
                __half2 h3 = __floats2half2_rn(o[6], o[7]);
                uint4 pk;
                pk.x = *(unsigned*)&h0; pk.y = *(unsigned*)&h1;
                pk.z = *(unsigned*)&h2; pk.w = *(unsigned*)&h3;
                *(uint4*)&OutH[(size_t)gr * 128 + col0] = pk;
            } else {
                *(float4*)&OutF[(size_t)gr * 128 + col0]     = *(float4*)(o);
                *(float4*)&OutF[(size_t)gr * 128 + col0 + 4] = *(float4*)(o + 4);
            }
        }
    }
}

// ---------------- launch ----------------
extern "C" void kernel_launch(void* const* d_in, const int* in_sizes, int n_in,
                              void* d_out, int out_size) {
    const float* x     = (const float*)d_in[0];
    const void*  ei    = d_in[1];
    const float* w0    = (const float*)d_in[2];
    const float* b0    = (const float*)d_in[3];
    const float* gamma = (const float*)d_in[4];
    const float* beta  = (const float*)d_in[5];
    const float* rmean = (const float*)d_in[6];
    const float* rvar  = (const float*)d_in[7];
    const float* w1    = (const float*)d_in[8];
    const float* b1    = (const float*)d_in[9];
    float*       out   = (float*)d_out;

    float *t0, *t1;
    __half *xh, *hh;
    int* cntp;
    cudaGetSymbolAddress((void**)&t0, g_t0);
    cudaGetSymbolAddress((void**)&t1, g_t1);
    cudaGetSymbolAddress((void**)&xh, g_xh);
    cudaGetSymbolAddress((void**)&hh, g_hh);
    cudaGetSymbolAddress((void**)&cntp, g_cnt);

    cudaFuncSetAttribute(k_gemm<true>,  cudaFuncAttributeMaxDynamicSharedMemorySize, SMEM_BYTES);
    cudaFuncSetAttribute(k_gemm<false>, cudaFuncAttributeMaxDynamicSharedMemorySize, SMEM_BYTES);

    // dtype probe + CSR build
    k_probe<<<1, 1024>>>((const int*)ei);
    cudaMemsetAsync(cntp, 0, NN * sizeof(int));
    k_count<<<(EE + 255) / 256, 256>>>(ei);
    k_bsum    <<<NBLK, SCAN_B>>>();
    k_bscan   <<<1, 512>>>();
    k_boffsets<<<NBLK, SCAN_B>>>();
    k_fill <<<(EE + 255) / 256, 256>>>(ei);

    // fp16 table of x
    k_tohalf<<<(NN * FF / 4 + 255) / 256, 256>>>(x, xh);

    const int GATHER_BLKS = (NN + 7) / 8;
    const int GEMM_BLKS   = (NN + 127) / 128;

    // layer 0
    k_gather_h<<<GATHER_BLKS, 256>>>(xh, t0);
    k_gemm<true><<<GEMM_BLKS, 256, SMEM_BYTES>>>(t0, w0, b0, gamma, beta, rmean, rvar,
                                                 nullptr, hh);
    // layer 1
    k_gather_h<<<GATHER_BLKS, 256>>>(hh, t1);
    k_gemm<false><<<GEMM_BLKS, 256, SMEM_BYTES>>>(t1, w1, b1, nullptr, nullptr, nullptr, nullptr,
                                                  out, nullptr);
}